// round 13
// baseline (speedup 1.0000x reference)
#include <cuda_runtime.h>
#include <cuda_bf16.h>
#include <math_constants.h>
#include <cstdint>

// Problem constants
#define BB 2
#define SS 2048
#define DD 1024
#define HH 16
#define DH 64
#define MM (BB * SS)   // 4096 rows for projections

#define CL2 0.18033688011112042f   // 0.125 * log2(e)

// ---------------------------------------------------------------------------
// Scratch buffers (__device__ globals; no allocation allowed)
// ---------------------------------------------------------------------------
__device__ __nv_bfloat16 g_Qp[MM * DD];    // projected Q (bf16, pre-scaled by CL2)
__device__ __nv_bfloat16 g_Kp[MM * DD];
__device__ __nv_bfloat16 g_Vp[MM * DD];
__device__ __nv_bfloat16 g_Qb[MM * DD];    // bf16 inputs
__device__ __nv_bfloat16 g_Kb[MM * DD];
__device__ __nv_bfloat16 g_Vb[MM * DD];
__device__ __nv_bfloat16 g_Wqt[DD * DD];   // W^T bf16: [n][k]
__device__ __nv_bfloat16 g_Wkt[DD * DD];
__device__ __nv_bfloat16 g_Wvt[DD * DD];

// ---------------------------------------------------------------------------
// PTX helpers
// ---------------------------------------------------------------------------
__device__ __forceinline__ uint32_t smem_u32(const void* p) {
    uint32_t a;
    asm("{ .reg .u64 t; cvta.to.shared.u64 t, %1; cvt.u32.u64 %0, t; }"
        : "=r"(a) : "l"(p));
    return a;
}

__device__ __forceinline__ void ldsm_x4(uint32_t* r, uint32_t addr) {
    asm volatile("ldmatrix.sync.aligned.m8n8.x4.shared.b16 {%0,%1,%2,%3}, [%4];"
                 : "=r"(r[0]), "=r"(r[1]), "=r"(r[2]), "=r"(r[3]) : "r"(addr));
}
__device__ __forceinline__ void ldsm_x4_t(uint32_t* r, uint32_t addr) {
    asm volatile("ldmatrix.sync.aligned.m8n8.x4.trans.shared.b16 {%0,%1,%2,%3}, [%4];"
                 : "=r"(r[0]), "=r"(r[1]), "=r"(r[2]), "=r"(r[3]) : "r"(addr));
}
__device__ __forceinline__ void mma_bf16(float* c, const uint32_t* a, const uint32_t* b) {
    asm volatile(
        "mma.sync.aligned.m16n8k16.row.col.f32.bf16.bf16.f32 "
        "{%0,%1,%2,%3}, {%4,%5,%6,%7}, {%8,%9}, {%0,%1,%2,%3};"
        : "+f"(c[0]), "+f"(c[1]), "+f"(c[2]), "+f"(c[3])
        : "r"(a[0]), "r"(a[1]), "r"(a[2]), "r"(a[3]), "r"(b[0]), "r"(b[1]));
}
__device__ __forceinline__ float ex2f(float x) {
    float y;
    asm("ex2.approx.ftz.f32 %0, %1;" : "=f"(y) : "f"(x));
    return y;
}

#define CP_ASYNC16(dst_u32, src_ptr) \
    asm volatile("cp.async.cg.shared.global [%0], [%1], 16;" \
                 :: "r"(dst_u32), "l"(src_ptr))
#define CP_COMMIT() asm volatile("cp.async.commit_group;" ::: "memory")
#define CP_WAIT_1() asm volatile("cp.async.wait_group 1;" ::: "memory")
#define CP_WAIT_0() asm volatile("cp.async.wait_group 0;" ::: "memory")

#define SW128(off) ((uint32_t)(off) ^ ((((uint32_t)(off)) >> 3) & 0x70u))

// ---------------------------------------------------------------------------
// Conversion kernels (proven bodies)
// ---------------------------------------------------------------------------
__global__ void __launch_bounds__(256)
f32_to_bf16_kernel(const float* __restrict__ in, __nv_bfloat16* __restrict__ out)
{
    int i = (blockIdx.x * 256 + threadIdx.x) * 4;
    float4 v = *(const float4*)(in + i);
    __nv_bfloat162* o2 = (__nv_bfloat162*)(out + i);
    o2[0] = __floats2bfloat162_rn(v.x, v.y);
    o2[1] = __floats2bfloat162_rn(v.z, v.w);
}

// Wt[n][k] = bf16(W[k][n]); W is [DD,DD] fp32 row-major
__global__ void __launch_bounds__(256)
transpose_to_bf16_kernel(const float* __restrict__ W, __nv_bfloat16* __restrict__ Wt)
{
    __shared__ float t[32][33];
    const int tx = threadIdx.x;
    const int ty = threadIdx.y;
    const int bx = blockIdx.x * 32;
    const int by = blockIdx.y * 32;
    #pragma unroll
    for (int i = 0; i < 4; i++)
        t[ty + i * 8][tx] = W[(size_t)(by + ty + i * 8) * DD + bx + tx];
    __syncthreads();
    #pragma unroll
    for (int i = 0; i < 4; i++)
        Wt[(size_t)(bx + ty + i * 8) * DD + by + tx] =
            __float2bfloat16(t[tx][ty + i * 8]);
}

// ---------------------------------------------------------------------------
// bf16 HMMA GEMM + bias, bf16 output (proven loop).
// Epilogue: out = bf16((acc + bias) * oscale)  (oscale=CL2 for Q, 1.0 else).
// ---------------------------------------------------------------------------
#define PBM 128
#define PBN 128
#define PBK 64
#define PKT (DD / PBK)     // 16 k-tiles
#define PSTG 16384
#define GEMM_SMEM (4 * PSTG + 128)

__global__ void __launch_bounds__(256)
gemm_bias_mma(const __nv_bfloat16* __restrict__ A,
              const __nv_bfloat16* __restrict__ Bt,
              const float* __restrict__ bias,
              __nv_bfloat16* __restrict__ C,
              float oscale)
{
    extern __shared__ char dyn[];
    const uint32_t sb = (smem_u32(dyn) + 127u) & ~127u;

    const int tid = threadIdx.x;
    const int lane = tid & 31;
    const int wid = tid >> 5;
    const int wm = wid >> 2;
    const int wn = wid & 3;
    const int n0 = blockIdx.x * PBN;
    const int m0 = blockIdx.y * PBM;

    const int rA = (lane & 7) + ((lane >> 3) & 1) * 8;
    const int kbA = (lane >> 4) * 16;
    const int rB = (lane & 7) + (lane >> 4) * 8;
    const int kbB = ((lane >> 3) & 1) * 16;

#define PROJ_ISSUE(T, BUF) do { \
    const uint32_t as_ = sb + (BUF) * 2 * PSTG; \
    const uint32_t bs_ = as_ + PSTG; \
    _Pragma("unroll") \
    for (int c = 0; c < 4; ++c) { \
        int id = tid + c * 256; \
        int row = id >> 3, c16 = id & 7; \
        uint32_t so = SW128(row * 128 + c16 * 16); \
        CP_ASYNC16(as_ + so, A  + (size_t)(m0 + row) * DD + (T) * PBK + c16 * 8); \
        CP_ASYNC16(bs_ + so, Bt + (size_t)(n0 + row) * DD + (T) * PBK + c16 * 8); \
    } \
} while (0)

    float acc[4][4][4] = {};

    PROJ_ISSUE(0, 0); CP_COMMIT();
    PROJ_ISSUE(1, 1); CP_COMMIT();
    CP_WAIT_1();
    __syncthreads();

    for (int t = 0; t < PKT; ++t) {
        const uint32_t as_ = sb + (t & 1) * 2 * PSTG;
        const uint32_t bs_ = as_ + PSTG;
        #pragma unroll
        for (int kk = 0; kk < 4; ++kk) {
            uint32_t af[4][4], bf[2][4];
            #pragma unroll
            for (int i = 0; i < 4; ++i)
                ldsm_x4(af[i], as_ + SW128((wm * 64 + i * 16 + rA) * 128 + kk * 32 + kbA));
            #pragma unroll
            for (int n16 = 0; n16 < 2; ++n16)
                ldsm_x4(bf[n16], bs_ + SW128((wn * 32 + n16 * 16 + rB) * 128 + kk * 32 + kbB));
            #pragma unroll
            for (int i = 0; i < 4; ++i)
                #pragma unroll
                for (int nb = 0; nb < 4; ++nb)
                    mma_bf16(acc[i][nb], af[i], &bf[nb >> 1][2 * (nb & 1)]);
        }
        __syncthreads();
        if (t + 2 < PKT) {
            PROJ_ISSUE(t + 2, t & 1); CP_COMMIT();
            CP_WAIT_1();
            __syncthreads();
        } else if (t + 1 < PKT) {
            CP_WAIT_0();
            __syncthreads();
        }
    }
#undef PROJ_ISSUE

    // Epilogue: (acc + bias) * oscale -> bf16
    const int gg = lane >> 2, cc = lane & 3;
    #pragma unroll
    for (int i = 0; i < 4; ++i) {
        int r0 = m0 + wm * 64 + i * 16 + gg;
        #pragma unroll
        for (int nb = 0; nb < 4; ++nb) {
            int cn = n0 + wn * 32 + nb * 8 + 2 * cc;
            float2 bi = *(const float2*)(bias + cn);
            *(__nv_bfloat162*)(C + (size_t)r0 * DD + cn) =
                __floats2bfloat162_rn((acc[i][nb][0] + bi.x) * oscale,
                                      (acc[i][nb][1] + bi.y) * oscale);
            *(__nv_bfloat162*)(C + (size_t)(r0 + 8) * DD + cn) =
                __floats2bfloat162_rn((acc[i][nb][2] + bi.x) * oscale,
                                      (acc[i][nb][3] + bi.y) * oscale);
        }
    }
}

// ---------------------------------------------------------------------------
// Flash attention, bf16 HMMA, NO-MAX softmax, CROSS-TILE SOFTWARE PIPELINE:
// loop body = QK(t) MMAs -> PV(t-1) MMAs (independent) -> exp(t) -> pa_prev.
// exp latency is hidden behind the next tile's tensor work. Bitwise-identical
// math to the previous version (same MMAs, same operands, reordered issue).
// 4-stage KV ring (live set {t-1, t, t+1, t+2} disjoint mod 4).
// ---------------------------------------------------------------------------
#define AQM 128
#define AKN 64
#define NKV (SS / AKN)     // 32 kv tiles
#define AOFF_Q 0
#define AOFF_K(s) (16384 + (s) * 16384)
#define AOFF_V(s) (16384 + (s) * 16384 + 8192)
#define ATTN_SMEM (16384 + 4 * 16384 + 128)   // 82048

__global__ void __launch_bounds__(256)
attn_mma(const __nv_bfloat16* __restrict__ Qp, const __nv_bfloat16* __restrict__ Kp,
         const __nv_bfloat16* __restrict__ Vp, const float* __restrict__ Xres,
         float* __restrict__ Out)
{
    extern __shared__ char dyn[];
    const uint32_t sb = (smem_u32(dyn) + 127u) & ~127u;

    const int tid = threadIdx.x;
    const int lane = tid & 31;
    const int wid = tid >> 5;
    const int qt = blockIdx.x;
    const int h  = blockIdx.y % HH;
    const int b  = blockIdx.y / HH;
    const int s0 = qt * AQM;
    const size_t headoff = (size_t)b * SS * DD + (size_t)h * DH;

    const int rA = (lane & 7) + ((lane >> 3) & 1) * 8;
    const int kbA = (lane >> 4) * 16;
    const int rB = (lane & 7) + (lane >> 4) * 8;
    const int kbB = ((lane >> 3) & 1) * 16;
    const int rV = (lane & 7) + ((lane >> 3) & 1) * 8;
    const int nbV = (lane >> 4) * 16;

#define KV_ISSUE(T, BUF) do { \
    _Pragma("unroll") \
    for (int c = 0; c < 2; ++c) { \
        int id = tid + c * 256; \
        int row = id >> 3, c16 = id & 7; \
        uint32_t so = SW128(row * 128 + c16 * 16); \
        size_t go = headoff + (size_t)((T) * AKN + row) * DD + c16 * 8; \
        CP_ASYNC16(sb + AOFF_K(BUF) + so, Kp + go); \
        CP_ASYNC16(sb + AOFF_V(BUF) + so, Vp + go); \
    } \
} while (0)

    {
        #pragma unroll
        for (int c = 0; c < 4; ++c) {
            int id = tid + c * 256;
            int row = id >> 3, c16 = id & 7;
            CP_ASYNC16(sb + AOFF_Q + SW128(row * 128 + c16 * 16),
                       Qp + headoff + (size_t)(s0 + row) * DD + c16 * 8);
        }
    }
    KV_ISSUE(0, 0); CP_COMMIT();
    KV_ISSUE(1, 1); CP_COMMIT();
    CP_WAIT_1();          // Q + KV0 landed
    __syncthreads();

    uint32_t qa[4][4];
    #pragma unroll
    for (int kk = 0; kk < 4; ++kk)
        ldsm_x4(qa[kk], sb + AOFF_Q + SW128((wid * 16 + rA) * 128 + kk * 32 + kbA));

    float Oacc[8][4] = {};
    float lrow[2] = {0.f, 0.f};
    uint32_t pa_prev[4][4];     // P fragments of tile t-1 (bf16x2 packed)

    for (int t = 0; t < NKV; ++t) {
        if (t > 0) {
            CP_WAIT_1();        // stage t landed (only t+1 pending)
            __syncthreads();    // all reads of stage t-2 complete
        }
        if (t + 2 < NKV) KV_ISSUE(t + 2, (t + 2) & 3);
        CP_COMMIT();

        const uint32_t ks_ = sb + AOFF_K(t & 3);

        // ---- S = Q @ K^T for tile t ----
        float Sacc[8][4] = {};
        #pragma unroll
        for (int kk = 0; kk < 4; ++kk) {
            uint32_t bk[4][4];
            #pragma unroll
            for (int n16 = 0; n16 < 4; ++n16)
                ldsm_x4(bk[n16], ks_ + SW128((n16 * 16 + rB) * 128 + kk * 32 + kbB));
            #pragma unroll
            for (int j = 0; j < 8; ++j)
                mma_bf16(Sacc[j], qa[kk], &bk[j >> 1][2 * (j & 1)]);
        }

        // ---- PV for tile t-1 (independent of exp(t); fills tensor pipe) ----
        if (t > 0) {
            const uint32_t vs_prev = sb + AOFF_V((t - 1) & 3);
            #pragma unroll
            for (int kk2 = 0; kk2 < 4; ++kk2) {
                uint32_t bv[4][4];
                #pragma unroll
                for (int n16 = 0; n16 < 4; ++n16)
                    ldsm_x4_t(bv[n16], vs_prev + SW128((kk2 * 16 + rV) * 128 + n16 * 32 + nbV));
                #pragma unroll
                for (int j = 0; j < 8; ++j)
                    mma_bf16(Oacc[j], pa_prev[kk2], &bv[j >> 1][2 * (j & 1)]);
            }
        }

        // ---- p = exp2(S(t)); pack into pa_prev; per-thread row sums ----
        #pragma unroll
        for (int j = 0; j < 8; ++j)
            #pragma unroll
            for (int x = 0; x < 4; ++x) {
                float pexp = ex2f(Sacc[j][x]);
                Sacc[j][x] = pexp;
                lrow[x >> 1] += pexp;
            }
        #pragma unroll
        for (int kk2 = 0; kk2 < 4; ++kk2) {
            __nv_bfloat162 t0 = __floats2bfloat162_rn(Sacc[2 * kk2][0], Sacc[2 * kk2][1]);
            __nv_bfloat162 t1 = __floats2bfloat162_rn(Sacc[2 * kk2][2], Sacc[2 * kk2][3]);
            __nv_bfloat162 t2 = __floats2bfloat162_rn(Sacc[2 * kk2 + 1][0], Sacc[2 * kk2 + 1][1]);
            __nv_bfloat162 t3 = __floats2bfloat162_rn(Sacc[2 * kk2 + 1][2], Sacc[2 * kk2 + 1][3]);
            pa_prev[kk2][0] = *(uint32_t*)&t0;
            pa_prev[kk2][1] = *(uint32_t*)&t1;
            pa_prev[kk2][2] = *(uint32_t*)&t2;
            pa_prev[kk2][3] = *(uint32_t*)&t3;
        }
    }
#undef KV_ISSUE

    // ---- drain: PV for the last tile ----
    {
        const uint32_t vs_last = sb + AOFF_V((NKV - 1) & 3);
        #pragma unroll
        for (int kk2 = 0; kk2 < 4; ++kk2) {
            uint32_t bv[4][4];
            #pragma unroll
            for (int n16 = 0; n16 < 4; ++n16)
                ldsm_x4_t(bv[n16], vs_last + SW128((kk2 * 16 + rV) * 128 + n16 * 32 + nbV));
            #pragma unroll
            for (int j = 0; j < 8; ++j)
                mma_bf16(Oacc[j], pa_prev[kk2], &bv[j >> 1][2 * (j & 1)]);
        }
    }

    #pragma unroll
    for (int r = 0; r < 2; ++r) {
        lrow[r] += __shfl_xor_sync(0xffffffffu, lrow[r], 1);
        lrow[r] += __shfl_xor_sync(0xffffffffu, lrow[r], 2);
    }
    const int gg = lane >> 2, cc = lane & 3;
    float inv[2] = {1.0f / lrow[0], 1.0f / lrow[1]};
    const int row0 = s0 + wid * 16 + gg;
    #pragma unroll
    for (int j = 0; j < 8; ++j) {
        int col = 8 * j + 2 * cc;
        size_t i0 = headoff + (size_t)row0 * DD + col;
        size_t i1 = headoff + (size_t)(row0 + 8) * DD + col;
        float2 r0 = *(const float2*)(Xres + i0);
        float2 r1 = *(const float2*)(Xres + i1);
        float2 o0 = {Oacc[j][0] * inv[0] + r0.x, Oacc[j][1] * inv[0] + r0.y};
        float2 o1 = {Oacc[j][2] * inv[1] + r1.x, Oacc[j][3] * inv[1] + r1.y};
        *(float2*)(Out + i0) = o0;
        *(float2*)(Out + i1) = o1;
    }
}

// ---------------------------------------------------------------------------
// Launch: 3 parallel capture branches (conv_i -> transpose_i -> gemm_i),
// joined before attention (round-12 proven structure).
// ---------------------------------------------------------------------------
extern "C" void kernel_launch(void* const* d_in, const int* in_sizes, int n_in,
                              void* d_out, int out_size)
{
    const float* queries = (const float*)d_in[0];
    const float* keys    = (const float*)d_in[1];
    const float* values  = (const float*)d_in[2];
    const float* Wq      = (const float*)d_in[3];
    const float* bq      = (const float*)d_in[4];
    const float* Wk      = (const float*)d_in[5];
    const float* bk      = (const float*)d_in[6];
    const float* Wv      = (const float*)d_in[7];
    const float* bv      = (const float*)d_in[8];
    float* out           = (float*)d_out;

    __nv_bfloat16 *dQp, *dKp, *dVp, *dQb, *dKb, *dVb, *dWqt, *dWkt, *dWvt;
    cudaGetSymbolAddress((void**)&dQp, g_Qp);
    cudaGetSymbolAddress((void**)&dKp, g_Kp);
    cudaGetSymbolAddress((void**)&dVp, g_Vp);
    cudaGetSymbolAddress((void**)&dQb, g_Qb);
    cudaGetSymbolAddress((void**)&dKb, g_Kb);
    cudaGetSymbolAddress((void**)&dVb, g_Vb);
    cudaGetSymbolAddress((void**)&dWqt, g_Wqt);
    cudaGetSymbolAddress((void**)&dWkt, g_Wkt);
    cudaGetSymbolAddress((void**)&dWvt, g_Wvt);

    cudaFuncSetAttribute(gemm_bias_mma,
                         cudaFuncAttributeMaxDynamicSharedMemorySize, GEMM_SMEM);
    cudaFuncSetAttribute(attn_mma,
                         cudaFuncAttributeMaxDynamicSharedMemorySize, ATTN_SMEM);

    static cudaStream_t br[3] = {nullptr, nullptr, nullptr};
    static cudaEvent_t eRoot = nullptr;
    static cudaEvent_t eBr[3] = {nullptr, nullptr, nullptr};
    if (br[0] == nullptr) {
        for (int i = 0; i < 3; ++i)
            cudaStreamCreateWithFlags(&br[i], cudaStreamNonBlocking);
        cudaEventCreateWithFlags(&eRoot, cudaEventDisableTiming);
        for (int i = 0; i < 3; ++i)
            cudaEventCreateWithFlags(&eBr[i], cudaEventDisableTiming);
    }

    const float* ins[3]        = {queries, keys, values};
    const float* Ws[3]         = {Wq, Wk, Wv};
    const float* bs[3]         = {bq, bk, bv};
    __nv_bfloat16* inb[3]      = {dQb, dKb, dVb};
    __nv_bfloat16* Wts[3]      = {dWqt, dWkt, dWvt};
    __nv_bfloat16* outp[3]     = {dQp, dKp, dVp};
    const float oscales[3]     = {CL2, 1.0f, 1.0f};

    cudaEventRecord(eRoot, 0);
    dim3 tgrid(DD / 32, DD / 32);
    dim3 tblk(32, 8);
    dim3 ggrid(DD / PBN, MM / PBM);   // (8, 32)
    for (int i = 0; i < 3; ++i) {
        cudaStreamWaitEvent(br[i], eRoot, 0);
        f32_to_bf16_kernel<<<MM * DD / 1024, 256, 0, br[i]>>>(ins[i], inb[i]);
        transpose_to_bf16_kernel<<<tgrid, tblk, 0, br[i]>>>(Ws[i], Wts[i]);
        gemm_bias_mma<<<ggrid, 256, GEMM_SMEM, br[i]>>>(inb[i], Wts[i], bs[i],
                                                        outp[i], oscales[i]);
        cudaEventRecord(eBr[i], br[i]);
    }
    for (int i = 0; i < 3; ++i)
        cudaStreamWaitEvent(0, eBr[i], 0);

    dim3 agrid(SS / AQM, HH * BB);    // (16, 32)
    attn_mma<<<agrid, 256, ATTN_SMEM>>>(dQp, dKp, dVp, queries, out);
}

// round 14
// speedup vs baseline: 1.0035x; 1.0035x over previous
#include <cuda_runtime.h>
#include <cuda_bf16.h>
#include <math_constants.h>
#include <cstdint>

// Problem constants
#define BB 2
#define SS 2048
#define DD 1024
#define HH 16
#define DH 64
#define MM (BB * SS)   // 4096 rows for projections

#define CL2 0.18033688011112042f   // 0.125 * log2(e)

// ---------------------------------------------------------------------------
// Scratch buffers (__device__ globals; no allocation allowed)
// ---------------------------------------------------------------------------
__device__ __nv_bfloat16 g_Qp[MM * DD];    // projected Q (bf16, pre-scaled by CL2)
__device__ __nv_bfloat16 g_Kp[MM * DD];
__device__ __nv_bfloat16 g_Vp[MM * DD];
__device__ __nv_bfloat16 g_Qb[MM * DD];    // bf16 inputs
__device__ __nv_bfloat16 g_Kb[MM * DD];
__device__ __nv_bfloat16 g_Vb[MM * DD];
__device__ __nv_bfloat16 g_Wqt[DD * DD];   // W^T bf16: [n][k]
__device__ __nv_bfloat16 g_Wkt[DD * DD];
__device__ __nv_bfloat16 g_Wvt[DD * DD];

// ---------------------------------------------------------------------------
// PTX helpers
// ---------------------------------------------------------------------------
__device__ __forceinline__ uint32_t smem_u32(const void* p) {
    uint32_t a;
    asm("{ .reg .u64 t; cvta.to.shared.u64 t, %1; cvt.u32.u64 %0, t; }"
        : "=r"(a) : "l"(p));
    return a;
}

__device__ __forceinline__ void ldsm_x4(uint32_t* r, uint32_t addr) {
    asm volatile("ldmatrix.sync.aligned.m8n8.x4.shared.b16 {%0,%1,%2,%3}, [%4];"
                 : "=r"(r[0]), "=r"(r[1]), "=r"(r[2]), "=r"(r[3]) : "r"(addr));
}
__device__ __forceinline__ void ldsm_x4_t(uint32_t* r, uint32_t addr) {
    asm volatile("ldmatrix.sync.aligned.m8n8.x4.trans.shared.b16 {%0,%1,%2,%3}, [%4];"
                 : "=r"(r[0]), "=r"(r[1]), "=r"(r[2]), "=r"(r[3]) : "r"(addr));
}
__device__ __forceinline__ void mma_bf16(float* c, const uint32_t* a, const uint32_t* b) {
    asm volatile(
        "mma.sync.aligned.m16n8k16.row.col.f32.bf16.bf16.f32 "
        "{%0,%1,%2,%3}, {%4,%5,%6,%7}, {%8,%9}, {%0,%1,%2,%3};"
        : "+f"(c[0]), "+f"(c[1]), "+f"(c[2]), "+f"(c[3])
        : "r"(a[0]), "r"(a[1]), "r"(a[2]), "r"(a[3]), "r"(b[0]), "r"(b[1]));
}
__device__ __forceinline__ float ex2f(float x) {
    float y;
    asm("ex2.approx.ftz.f32 %0, %1;" : "=f"(y) : "f"(x));
    return y;
}

#define CP_ASYNC16(dst_u32, src_ptr) \
    asm volatile("cp.async.cg.shared.global [%0], [%1], 16;" \
                 :: "r"(dst_u32), "l"(src_ptr))
#define CP_COMMIT() asm volatile("cp.async.commit_group;" ::: "memory")
#define CP_WAIT_1() asm volatile("cp.async.wait_group 1;" ::: "memory")
#define CP_WAIT_0() asm volatile("cp.async.wait_group 0;" ::: "memory")

#define SW128(off) ((uint32_t)(off) ^ ((((uint32_t)(off)) >> 3) & 0x70u))

// ---------------------------------------------------------------------------
// Conversion kernels (proven bodies)
// ---------------------------------------------------------------------------
__global__ void __launch_bounds__(256)
f32_to_bf16_kernel(const float* __restrict__ in, __nv_bfloat16* __restrict__ out)
{
    int i = (blockIdx.x * 256 + threadIdx.x) * 4;
    float4 v = *(const float4*)(in + i);
    __nv_bfloat162* o2 = (__nv_bfloat162*)(out + i);
    o2[0] = __floats2bfloat162_rn(v.x, v.y);
    o2[1] = __floats2bfloat162_rn(v.z, v.w);
}

// Wt[n][k] = bf16(W[k][n]); W is [DD,DD] fp32 row-major
__global__ void __launch_bounds__(256)
transpose_to_bf16_kernel(const float* __restrict__ W, __nv_bfloat16* __restrict__ Wt)
{
    __shared__ float t[32][33];
    const int tx = threadIdx.x;
    const int ty = threadIdx.y;
    const int bx = blockIdx.x * 32;
    const int by = blockIdx.y * 32;
    #pragma unroll
    for (int i = 0; i < 4; i++)
        t[ty + i * 8][tx] = W[(size_t)(by + ty + i * 8) * DD + bx + tx];
    __syncthreads();
    #pragma unroll
    for (int i = 0; i < 4; i++)
        Wt[(size_t)(bx + ty + i * 8) * DD + by + tx] =
            __float2bfloat16(t[tx][ty + i * 8]);
}

// ---------------------------------------------------------------------------
// bf16 HMMA GEMM + bias, bf16 output (proven loop).
// Epilogue: out = bf16((acc + bias) * oscale)  (oscale=CL2 for Q, 1.0 else).
// ---------------------------------------------------------------------------
#define PBM 128
#define PBN 128
#define PBK 64
#define PKT (DD / PBK)     // 16 k-tiles
#define PSTG 16384
#define GEMM_SMEM (4 * PSTG + 128)

__global__ void __launch_bounds__(256)
gemm_bias_mma(const __nv_bfloat16* __restrict__ A,
              const __nv_bfloat16* __restrict__ Bt,
              const float* __restrict__ bias,
              __nv_bfloat16* __restrict__ C,
              float oscale)
{
    extern __shared__ char dyn[];
    const uint32_t sb = (smem_u32(dyn) + 127u) & ~127u;

    const int tid = threadIdx.x;
    const int lane = tid & 31;
    const int wid = tid >> 5;
    const int wm = wid >> 2;
    const int wn = wid & 3;
    const int n0 = blockIdx.x * PBN;
    const int m0 = blockIdx.y * PBM;

    const int rA = (lane & 7) + ((lane >> 3) & 1) * 8;
    const int kbA = (lane >> 4) * 16;
    const int rB = (lane & 7) + (lane >> 4) * 8;
    const int kbB = ((lane >> 3) & 1) * 16;

#define PROJ_ISSUE(T, BUF) do { \
    const uint32_t as_ = sb + (BUF) * 2 * PSTG; \
    const uint32_t bs_ = as_ + PSTG; \
    _Pragma("unroll") \
    for (int c = 0; c < 4; ++c) { \
        int id = tid + c * 256; \
        int row = id >> 3, c16 = id & 7; \
        uint32_t so = SW128(row * 128 + c16 * 16); \
        CP_ASYNC16(as_ + so, A  + (size_t)(m0 + row) * DD + (T) * PBK + c16 * 8); \
        CP_ASYNC16(bs_ + so, Bt + (size_t)(n0 + row) * DD + (T) * PBK + c16 * 8); \
    } \
} while (0)

    float acc[4][4][4] = {};

    PROJ_ISSUE(0, 0); CP_COMMIT();
    PROJ_ISSUE(1, 1); CP_COMMIT();
    CP_WAIT_1();
    __syncthreads();

    for (int t = 0; t < PKT; ++t) {
        const uint32_t as_ = sb + (t & 1) * 2 * PSTG;
        const uint32_t bs_ = as_ + PSTG;
        #pragma unroll
        for (int kk = 0; kk < 4; ++kk) {
            uint32_t af[4][4], bf[2][4];
            #pragma unroll
            for (int i = 0; i < 4; ++i)
                ldsm_x4(af[i], as_ + SW128((wm * 64 + i * 16 + rA) * 128 + kk * 32 + kbA));
            #pragma unroll
            for (int n16 = 0; n16 < 2; ++n16)
                ldsm_x4(bf[n16], bs_ + SW128((wn * 32 + n16 * 16 + rB) * 128 + kk * 32 + kbB));
            #pragma unroll
            for (int i = 0; i < 4; ++i)
                #pragma unroll
                for (int nb = 0; nb < 4; ++nb)
                    mma_bf16(acc[i][nb], af[i], &bf[nb >> 1][2 * (nb & 1)]);
        }
        __syncthreads();
        if (t + 2 < PKT) {
            PROJ_ISSUE(t + 2, t & 1); CP_COMMIT();
            CP_WAIT_1();
            __syncthreads();
        } else if (t + 1 < PKT) {
            CP_WAIT_0();
            __syncthreads();
        }
    }
#undef PROJ_ISSUE

    // Epilogue: (acc + bias) * oscale -> bf16
    const int gg = lane >> 2, cc = lane & 3;
    #pragma unroll
    for (int i = 0; i < 4; ++i) {
        int r0 = m0 + wm * 64 + i * 16 + gg;
        #pragma unroll
        for (int nb = 0; nb < 4; ++nb) {
            int cn = n0 + wn * 32 + nb * 8 + 2 * cc;
            float2 bi = *(const float2*)(bias + cn);
            *(__nv_bfloat162*)(C + (size_t)r0 * DD + cn) =
                __floats2bfloat162_rn((acc[i][nb][0] + bi.x) * oscale,
                                      (acc[i][nb][1] + bi.y) * oscale);
            *(__nv_bfloat162*)(C + (size_t)(r0 + 8) * DD + cn) =
                __floats2bfloat162_rn((acc[i][nb][2] + bi.x) * oscale,
                                      (acc[i][nb][3] + bi.y) * oscale);
        }
    }
}

// ---------------------------------------------------------------------------
// PERSISTENT flash attention, bf16 HMMA, NO-MAX softmax.
// Body = round-12 proven version (3-stage ring, depth-2 prefetch, 2 CTA/SM).
// Grid = 296 CTAs (2/SM x 148); each grid-strides over 512 (qt,h,b) units,
// removing the 2nd-wave launch bubble (1.73 waves ran as 2.0 before).
// Consecutive CTAs share (h,b) -> K/V L2 reuse.
// ---------------------------------------------------------------------------
#define AQM 128
#define AKN 64
#define NKV (SS / AKN)     // 32 kv tiles
#define NUNITS ((SS / AQM) * HH * BB)   // 512
#define AOFF_Q 0
#define AOFF_K(s) (16384 + (s) * 16384)
#define AOFF_V(s) (16384 + (s) * 16384 + 8192)
#define ATTN_SMEM (65536 + 128)
#define ATTN_GRID 296

__global__ void __launch_bounds__(256, 2)
attn_mma(const __nv_bfloat16* __restrict__ Qp, const __nv_bfloat16* __restrict__ Kp,
         const __nv_bfloat16* __restrict__ Vp, const float* __restrict__ Xres,
         float* __restrict__ Out)
{
    extern __shared__ char dyn[];
    const uint32_t sb = (smem_u32(dyn) + 127u) & ~127u;

    const int tid = threadIdx.x;
    const int lane = tid & 31;
    const int wid = tid >> 5;

    const int rA = (lane & 7) + ((lane >> 3) & 1) * 8;
    const int kbA = (lane >> 4) * 16;
    const int rB = (lane & 7) + (lane >> 4) * 8;
    const int kbB = ((lane >> 3) & 1) * 16;
    const int rV = (lane & 7) + ((lane >> 3) & 1) * 8;
    const int nbV = (lane >> 4) * 16;

    for (int unit = blockIdx.x; unit < NUNITS; unit += gridDim.x) {
        const int qt = unit & 15;          // 16 q-tiles
        const int hb = unit >> 4;          // (h,b): 0..31
        const int h  = hb % HH;
        const int b  = hb / HH;
        const int s0 = qt * AQM;
        const size_t headoff = (size_t)b * SS * DD + (size_t)h * DH;

        // all warps must be done reading smem from the previous unit
        // before the new prologue overwrites buffers 0/1
        __syncthreads();

#define KV_ISSUE(T, BUF) do { \
    _Pragma("unroll") \
    for (int c = 0; c < 2; ++c) { \
        int id = tid + c * 256; \
        int row = id >> 3, c16 = id & 7; \
        uint32_t so = SW128(row * 128 + c16 * 16); \
        size_t go = headoff + (size_t)((T) * AKN + row) * DD + c16 * 8; \
        CP_ASYNC16(sb + AOFF_K(BUF) + so, Kp + go); \
        CP_ASYNC16(sb + AOFF_V(BUF) + so, Vp + go); \
    } \
} while (0)

        {
            #pragma unroll
            for (int c = 0; c < 4; ++c) {
                int id = tid + c * 256;
                int row = id >> 3, c16 = id & 7;
                CP_ASYNC16(sb + AOFF_Q + SW128(row * 128 + c16 * 16),
                           Qp + headoff + (size_t)(s0 + row) * DD + c16 * 8);
            }
        }
        KV_ISSUE(0, 0); CP_COMMIT();
        KV_ISSUE(1, 1); CP_COMMIT();
        CP_WAIT_1();
        __syncthreads();

        uint32_t qa[4][4];
        #pragma unroll
        for (int kk = 0; kk < 4; ++kk)
            ldsm_x4(qa[kk], sb + AOFF_Q + SW128((wid * 16 + rA) * 128 + kk * 32 + kbA));

        float Oacc[8][4] = {};
        float lrow[2] = {0.f, 0.f};

        for (int t = 0; t < NKV; ++t) {
            if (t > 0) {
                CP_WAIT_1();
                __syncthreads();
            }
            if (t + 2 < NKV) KV_ISSUE(t + 2, (t + 2) % 3);
            CP_COMMIT();

            const uint32_t ks_ = sb + AOFF_K(t % 3);
            const uint32_t vs_ = sb + AOFF_V(t % 3);

            float Sacc[8][4] = {};
            #pragma unroll
            for (int kk = 0; kk < 4; ++kk) {
                uint32_t bk[4][4];
                #pragma unroll
                for (int n16 = 0; n16 < 4; ++n16)
                    ldsm_x4(bk[n16], ks_ + SW128((n16 * 16 + rB) * 128 + kk * 32 + kbB));
                #pragma unroll
                for (int j = 0; j < 8; ++j)
                    mma_bf16(Sacc[j], qa[kk], &bk[j >> 1][2 * (j & 1)]);
            }

            // ---- p = exp2(S) (Q pre-scaled; no per-element multiply) ----
            #pragma unroll
            for (int j = 0; j < 8; ++j)
                #pragma unroll
                for (int x = 0; x < 4; ++x) {
                    float pexp = ex2f(Sacc[j][x]);
                    Sacc[j][x] = pexp;
                    lrow[x >> 1] += pexp;
                }

            #pragma unroll
            for (int kk2 = 0; kk2 < 4; ++kk2) {
                uint32_t pa[4];
                {
                    __nv_bfloat162 t0 = __floats2bfloat162_rn(Sacc[2 * kk2][0], Sacc[2 * kk2][1]);
                    __nv_bfloat162 t1 = __floats2bfloat162_rn(Sacc[2 * kk2][2], Sacc[2 * kk2][3]);
                    __nv_bfloat162 t2 = __floats2bfloat162_rn(Sacc[2 * kk2 + 1][0], Sacc[2 * kk2 + 1][1]);
                    __nv_bfloat162 t3 = __floats2bfloat162_rn(Sacc[2 * kk2 + 1][2], Sacc[2 * kk2 + 1][3]);
                    pa[0] = *(uint32_t*)&t0; pa[1] = *(uint32_t*)&t1;
                    pa[2] = *(uint32_t*)&t2; pa[3] = *(uint32_t*)&t3;
                }
                uint32_t bv[4][4];
                #pragma unroll
                for (int n16 = 0; n16 < 4; ++n16)
                    ldsm_x4_t(bv[n16], vs_ + SW128((kk2 * 16 + rV) * 128 + n16 * 32 + nbV));
                #pragma unroll
                for (int j = 0; j < 8; ++j)
                    mma_bf16(Oacc[j], pa, &bv[j >> 1][2 * (j & 1)]);
            }
        }
#undef KV_ISSUE

        #pragma unroll
        for (int r = 0; r < 2; ++r) {
            lrow[r] += __shfl_xor_sync(0xffffffffu, lrow[r], 1);
            lrow[r] += __shfl_xor_sync(0xffffffffu, lrow[r], 2);
        }
        const int gg = lane >> 2, cc = lane & 3;
        float inv[2] = {1.0f / lrow[0], 1.0f / lrow[1]};
        const int row0 = s0 + wid * 16 + gg;
        #pragma unroll
        for (int j = 0; j < 8; ++j) {
            int col = 8 * j + 2 * cc;
            size_t i0 = headoff + (size_t)row0 * DD + col;
            size_t i1 = headoff + (size_t)(row0 + 8) * DD + col;
            float2 r0 = *(const float2*)(Xres + i0);
            float2 r1 = *(const float2*)(Xres + i1);
            float2 o0 = {Oacc[j][0] * inv[0] + r0.x, Oacc[j][1] * inv[0] + r0.y};
            float2 o1 = {Oacc[j][2] * inv[1] + r1.x, Oacc[j][3] * inv[1] + r1.y};
            *(float2*)(Out + i0) = o0;
            *(float2*)(Out + i1) = o1;
        }
    }
}

// ---------------------------------------------------------------------------
// Launch: 3 parallel capture branches (conv_i -> transpose_i -> gemm_i),
// joined before the persistent attention (round-12 proven structure).
// ---------------------------------------------------------------------------
extern "C" void kernel_launch(void* const* d_in, const int* in_sizes, int n_in,
                              void* d_out, int out_size)
{
    const float* queries = (const float*)d_in[0];
    const float* keys    = (const float*)d_in[1];
    const float* values  = (const float*)d_in[2];
    const float* Wq      = (const float*)d_in[3];
    const float* bq      = (const float*)d_in[4];
    const float* Wk      = (const float*)d_in[5];
    const float* bk      = (const float*)d_in[6];
    const float* Wv      = (const float*)d_in[7];
    const float* bv      = (const float*)d_in[8];
    float* out           = (float*)d_out;

    __nv_bfloat16 *dQp, *dKp, *dVp, *dQb, *dKb, *dVb, *dWqt, *dWkt, *dWvt;
    cudaGetSymbolAddress((void**)&dQp, g_Qp);
    cudaGetSymbolAddress((void**)&dKp, g_Kp);
    cudaGetSymbolAddress((void**)&dVp, g_Vp);
    cudaGetSymbolAddress((void**)&dQb, g_Qb);
    cudaGetSymbolAddress((void**)&dKb, g_Kb);
    cudaGetSymbolAddress((void**)&dVb, g_Vb);
    cudaGetSymbolAddress((void**)&dWqt, g_Wqt);
    cudaGetSymbolAddress((void**)&dWkt, g_Wkt);
    cudaGetSymbolAddress((void**)&dWvt, g_Wvt);

    cudaFuncSetAttribute(gemm_bias_mma,
                         cudaFuncAttributeMaxDynamicSharedMemorySize, GEMM_SMEM);
    cudaFuncSetAttribute(attn_mma,
                         cudaFuncAttributeMaxDynamicSharedMemorySize, ATTN_SMEM);

    static cudaStream_t br[3] = {nullptr, nullptr, nullptr};
    static cudaEvent_t eRoot = nullptr;
    static cudaEvent_t eBr[3] = {nullptr, nullptr, nullptr};
    if (br[0] == nullptr) {
        for (int i = 0; i < 3; ++i)
            cudaStreamCreateWithFlags(&br[i], cudaStreamNonBlocking);
        cudaEventCreateWithFlags(&eRoot, cudaEventDisableTiming);
        for (int i = 0; i < 3; ++i)
            cudaEventCreateWithFlags(&eBr[i], cudaEventDisableTiming);
    }

    const float* ins[3]        = {queries, keys, values};
    const float* Ws[3]         = {Wq, Wk, Wv};
    const float* bs[3]         = {bq, bk, bv};
    __nv_bfloat16* inb[3]      = {dQb, dKb, dVb};
    __nv_bfloat16* Wts[3]      = {dWqt, dWkt, dWvt};
    __nv_bfloat16* outp[3]     = {dQp, dKp, dVp};
    const float oscales[3]     = {CL2, 1.0f, 1.0f};

    cudaEventRecord(eRoot, 0);
    dim3 tgrid(DD / 32, DD / 32);
    dim3 tblk(32, 8);
    dim3 ggrid(DD / PBN, MM / PBM);   // (8, 32)
    for (int i = 0; i < 3; ++i) {
        cudaStreamWaitEvent(br[i], eRoot, 0);
        f32_to_bf16_kernel<<<MM * DD / 1024, 256, 0, br[i]>>>(ins[i], inb[i]);
        transpose_to_bf16_kernel<<<tgrid, tblk, 0, br[i]>>>(Ws[i], Wts[i]);
        gemm_bias_mma<<<ggrid, 256, GEMM_SMEM, br[i]>>>(inb[i], Wts[i], bs[i],
                                                        outp[i], oscales[i]);
        cudaEventRecord(eBr[i], br[i]);
    }
    for (int i = 0; i < 3; ++i)
        cudaStreamWaitEvent(0, eBr[i], 0);

    // persistent attention: 296 CTAs grid-stride over 512 units
    attn_mma<<<ATTN_GRID, 256, ATTN_SMEM>>>(dQp, dKp, dVp, queries, out);
}